// round 7
// baseline (speedup 1.0000x reference)
#include <cuda_runtime.h>
#include <cstdint>

// DeepseekV4Compressor on GB300 (sm_103, portable target — tcgen05 unavailable)
// B=4, S=4096, H=4096, HD=512, RATIO=4, C=1024, ROPE=64
//
//  1) round_x_kernel : RNA-round x -> tf32 bits, k-permuted per 8-block -> g_xr
//  2) round_w_kernel : same + interleave W_kv/W_gate at 64-feature granularity
//  3) gemm_kernel    : mma.sync m16n8k8 tf32, CTA 256x128, 3-stage cp.async,
//                      fused epilogue y2 = kv * sigmoid(gate) -> g_y2
//  4) combine_kernel : softmax(ape) combine + RMSNorm + RoPE -> out

// ------------------------- static device scratch -----------------------------
static __device__ float g_xr[67108864];   // 256 MB  [16384, 4096] rounded+permuted x
static __device__ float g_wc[8388608];    //  32 MB  [2048, 4096]  rounded+permuted W
static __device__ float g_y2[16777216];   //  64 MB  [16384, 1024] kv*sigmoid(gate)

// ------------------------------ helpers --------------------------------------
__device__ __forceinline__ float tf32_rna(float f) {
    uint32_t u; asm("cvt.rna.tf32.f32 %0, %1;" : "=r"(u) : "f"(f));
    return __uint_as_float(u);
}
__device__ __forceinline__ uint32_t smem_u32(const void* p) {
    uint32_t a;
    asm("{ .reg .u64 t; cvta.to.shared.u64 t, %1; cvt.u32.u64 %0, t; }" : "=r"(a) : "l"(p));
    return a;
}
__device__ __forceinline__ void cp_async16(uint32_t dst, const void* src) {
    asm volatile("cp.async.cg.shared.global [%0], [%1], 16;" :: "r"(dst), "l"(src));
}
#define CP_COMMIT() asm volatile("cp.async.commit_group;" ::: "memory")

__device__ __forceinline__ void mma_tf32(float& d0, float& d1, float& d2, float& d3,
                                         uint32_t a0, uint32_t a1, uint32_t a2, uint32_t a3,
                                         uint32_t b0, uint32_t b1) {
    asm volatile("mma.sync.aligned.m16n8k8.row.col.f32.tf32.tf32.f32 "
                 "{%0,%1,%2,%3}, {%4,%5,%6,%7}, {%8,%9}, {%0,%1,%2,%3};"
                 : "+f"(d0), "+f"(d1), "+f"(d2), "+f"(d3)
                 : "r"(a0), "r"(a1), "r"(a2), "r"(a3), "r"(b0), "r"(b1));
}
__device__ __forceinline__ float sigmoidf_(float x) {
    return 1.0f / (1.0f + __expf(-x));
}

// k-permutation within each 8-block: pos 2c <- k=c, pos 2c+1 <- k=c+4.
// Applied identically to x and W rows, so dot products are unchanged, and a
// fragment pair (k, k+4) is 8 contiguous bytes in smem -> one LDS.64.
__device__ __forceinline__ void perm_round8(const float4& i0, const float4& i1,
                                            float4& o0, float4& o1) {
    o0 = make_float4(tf32_rna(i0.x), tf32_rna(i1.x), tf32_rna(i0.y), tf32_rna(i1.y));
    o1 = make_float4(tf32_rna(i0.z), tf32_rna(i1.z), tf32_rna(i0.w), tf32_rna(i1.w));
}

// ----------------------------- rounding passes -------------------------------
__global__ void round_x_kernel(const float4* __restrict__ x) {
    size_t gidx = (size_t)blockIdx.x * 256 + threadIdx.x;   // 8,388,608 groups of 8
    float4 i0 = x[gidx * 2], i1 = x[gidx * 2 + 1];
    float4 o0, o1;
    perm_round8(i0, i1, o0, o1);
    float4* dst = reinterpret_cast<float4*>(g_xr) + gidx * 2;
    dst[0] = o0; dst[1] = o1;
}

__global__ void round_w_kernel(const float* __restrict__ wkv, const float* __restrict__ wg) {
    int o2 = blockIdx.x;                      // 0..2047 dest row in g_wc
    int nb = o2 >> 7;                         // 128-row block (16 blocks)
    int half = (o2 >> 6) & 1;                 // 0 = kv, 1 = gate
    int idx = o2 & 63;
    const float4* src = reinterpret_cast<const float4*>(
        (half ? wg : wkv) + (size_t)(nb * 64 + idx) * 4096);
    float4* dst = reinterpret_cast<float4*>(g_wc + (size_t)o2 * 4096);
    #pragma unroll
    for (int j = 0; j < 2; ++j) {
        int gq = threadIdx.x + j * 256;       // 512 groups per row
        float4 i0 = src[gq * 2], i1 = src[gq * 2 + 1];
        float4 o0, o1;
        perm_round8(i0, i1, o0, o1);
        dst[gq * 2] = o0; dst[gq * 2 + 1] = o1;
    }
}

// --------------------------------- GEMM --------------------------------------
// CTA 256(M) x 128(N), BK=32. 8 warps (4m x 2n), warp tile 64x64.
// smem row = 32 floats padded to 40 (160 B): fragment LDS.64s are 2-phase
// bank-uniform; cp.async row chunks are 4-phase uniform.
#define ROWB    160
#define A_BYTES (256 * ROWB)              // 40960
#define B_BYTES (128 * ROWB)              // 20480
#define STAGE   (A_BYTES + B_BYTES)       // 61440
#define NSTAGE  3
#define SMEM_BYTES (NSTAGE * STAGE)       // 184320
#define NT      128                       // K / 32

__device__ __forceinline__ void load_stage(uint32_t sb, int s, int kt,
                                           int bm, int bn, int tid) {
    uint32_t st = sb + (uint32_t)s * STAGE;
    const float* Ag = g_xr + ((size_t)bm * 256) * 4096 + (size_t)kt * 32;
    const float* Bg = g_wc + ((size_t)bn * 128) * 4096 + (size_t)kt * 32;
    #pragma unroll
    for (int i = 0; i < 12; ++i) {
        int q = tid + i * 256;                 // 0..3071 16B-chunks
        if (q < 2048) {                        // A: 256 rows x 8 chunks
            int r = q >> 3, c = q & 7;
            cp_async16(st + (uint32_t)(r * ROWB + c * 16), Ag + (size_t)r * 4096 + c * 4);
        } else {                               // B: 128 rows x 8 chunks
            int q2 = q - 2048;
            int r = q2 >> 3, c = q2 & 7;
            cp_async16(st + A_BYTES + (uint32_t)(r * ROWB + c * 16),
                       Bg + (size_t)r * 4096 + c * 4);
        }
    }
}

__global__ void __launch_bounds__(256, 1) gemm_kernel() {
    extern __shared__ char smem[];
    const uint32_t sb = smem_u32(smem);
    const int tid = threadIdx.x;
    const int lane = tid & 31, wid = tid >> 5;
    const int wm = wid >> 1, wn = wid & 1;
    const int g = lane >> 2, t = lane & 3;
    const int bn = blockIdx.x & 15;            // n fastest: A panel L2 reuse
    const int bm = blockIdx.x >> 4;

    float acc[4][8][4];
    #pragma unroll
    for (int i = 0; i < 4; ++i)
        #pragma unroll
        for (int j = 0; j < 8; ++j)
            #pragma unroll
            for (int r = 0; r < 4; ++r) acc[i][j][r] = 0.0f;

    load_stage(sb, 0, 0, bm, bn, tid); CP_COMMIT();
    load_stage(sb, 1, 1, bm, bn, tid); CP_COMMIT();

    for (int it = 0; it < NT; ++it) {
        asm volatile("cp.async.wait_group 1;" ::: "memory");   // Ktile 'it' resident
        __syncthreads();

        int ld = it + 2;
        if (ld < NT) load_stage(sb, ld % 3, ld, bm, bn, tid);
        CP_COMMIT();

        const uint32_t st = sb + (uint32_t)(it % 3) * STAGE;
        const uint32_t aB = st + (uint32_t)((wm * 64 + g) * ROWB + t * 8);
        const uint32_t bB = st + A_BYTES + (uint32_t)((wn * 64 + g) * ROWB + t * 8);
        #pragma unroll
        for (int ks = 0; ks < 4; ++ks) {
            uint32_t afr[4][4];
            #pragma unroll
            for (int i = 0; i < 4; ++i) {
                uint32_t p0, p1, q0, q1;
                asm volatile("ld.shared.v2.b32 {%0,%1}, [%2];"
                             : "=r"(p0), "=r"(p1) : "r"(aB + i * 16 * ROWB + ks * 32));
                asm volatile("ld.shared.v2.b32 {%0,%1}, [%2];"
                             : "=r"(q0), "=r"(q1) : "r"(aB + i * 16 * ROWB + 8 * ROWB + ks * 32));
                afr[i][0] = p0; afr[i][2] = p1;   // (g, k), (g, k+4)
                afr[i][1] = q0; afr[i][3] = q1;   // (g+8, k), (g+8, k+4)
            }
            #pragma unroll
            for (int j = 0; j < 8; ++j) {
                uint32_t b0, b1;
                asm volatile("ld.shared.v2.b32 {%0,%1}, [%2];"
                             : "=r"(b0), "=r"(b1) : "r"(bB + j * 8 * ROWB + ks * 32));
                #pragma unroll
                for (int i = 0; i < 4; ++i)
                    mma_tf32(acc[i][j][0], acc[i][j][1], acc[i][j][2], acc[i][j][3],
                             afr[i][0], afr[i][1], afr[i][2], afr[i][3], b0, b1);
            }
        }
    }

    // ---------------- epilogue: y2 = kv * sigmoid(gate) ----------------------
    __syncthreads();                           // all warps done reading stages
    // gate warps (wn=1) write sigmoid to smem [256][68 floats]
    if (wn == 1) {
        #pragma unroll
        for (int i = 0; i < 4; ++i) {
            int row0 = wm * 64 + i * 16 + g;
            #pragma unroll
            for (int j = 0; j < 8; ++j) {
                int col = j * 8 + 2 * t;
                float2 s0 = make_float2(sigmoidf_(acc[i][j][0]), sigmoidf_(acc[i][j][1]));
                float2 s1 = make_float2(sigmoidf_(acc[i][j][2]), sigmoidf_(acc[i][j][3]));
                *reinterpret_cast<float2*>(smem + row0 * 272 + col * 4) = s0;
                *reinterpret_cast<float2*>(smem + (row0 + 8) * 272 + col * 4) = s1;
            }
        }
    }
    __syncthreads();
    if (wn == 0) {                             // kv warps fuse and store
        #pragma unroll
        for (int i = 0; i < 4; ++i) {
            int row0 = wm * 64 + i * 16 + g;
            #pragma unroll
            for (int j = 0; j < 8; ++j) {
                int col = j * 8 + 2 * t;
                float2 s0 = *reinterpret_cast<float2*>(smem + row0 * 272 + col * 4);
                float2 s1 = *reinterpret_cast<float2*>(smem + (row0 + 8) * 272 + col * 4);
                float2 y0 = make_float2(acc[i][j][0] * s0.x, acc[i][j][1] * s0.y);
                float2 y1 = make_float2(acc[i][j][2] * s1.x, acc[i][j][3] * s1.y);
                size_t base = ((size_t)(bm * 256 + row0)) * 1024 + (size_t)bn * 64 + col;
                *reinterpret_cast<float2*>(g_y2 + base) = y0;
                *reinterpret_cast<float2*>(g_y2 + base + 8 * 1024) = y1;
            }
        }
    }
}

// ------------------------------- combine -------------------------------------
__global__ void __launch_bounds__(128) combine_kernel(
    const float* __restrict__ cosb, const float* __restrict__ sinb,
    const float* __restrict__ ape,  const float* __restrict__ norm_w,
    float* __restrict__ out)
{
    __shared__ float s_out[512];
    __shared__ float s_red[4];
    const int c = blockIdx.x, b = blockIdx.y;
    const int tid = threadIdx.x;
    const size_t rowb = (size_t)b * 4096 + (size_t)c * 4;

    float acc[4];
    float ss = 0.0f;
    #pragma unroll
    for (int kk = 0; kk < 4; ++kk) {
        const int d = tid + kk * 128;
        float a0 = ape[d],        a1 = ape[1024 + d];
        float a2 = ape[2048 + d], a3 = ape[3072 + d];
        float m0 = g_y2[(rowb + 0) * 1024 + d];
        float m1 = g_y2[(rowb + 1) * 1024 + d];
        float m2 = g_y2[(rowb + 2) * 1024 + d];
        float m3 = g_y2[(rowb + 3) * 1024 + d];
        float v;
        if (c == 0) {
            float mx = fmaxf(fmaxf(a0, a1), fmaxf(a2, a3));
            float e0 = __expf(a0 - mx), e1 = __expf(a1 - mx);
            float e2 = __expf(a2 - mx), e3 = __expf(a3 - mx);
            float inv = 1.0f / (e0 + e1 + e2 + e3);
            v = (m0 * e0 + m1 * e1 + m2 * e2 + m3 * e3) * inv;
        } else {
            float b0 = ape[512 + d],  b1 = ape[1536 + d];
            float b2 = ape[2560 + d], b3 = ape[3584 + d];
            float o0 = g_y2[(rowb - 4 + 0) * 1024 + 512 + d];
            float o1 = g_y2[(rowb - 4 + 1) * 1024 + 512 + d];
            float o2 = g_y2[(rowb - 4 + 2) * 1024 + 512 + d];
            float o3 = g_y2[(rowb - 4 + 3) * 1024 + 512 + d];
            float mx = fmaxf(fmaxf(fmaxf(a0, a1), fmaxf(a2, a3)),
                             fmaxf(fmaxf(b0, b1), fmaxf(b2, b3)));
            float e0 = __expf(a0 - mx), e1 = __expf(a1 - mx);
            float e2 = __expf(a2 - mx), e3 = __expf(a3 - mx);
            float e4 = __expf(b0 - mx), e5 = __expf(b1 - mx);
            float e6 = __expf(b2 - mx), e7 = __expf(b3 - mx);
            float inv = 1.0f / (e0 + e1 + e2 + e3 + e4 + e5 + e6 + e7);
            v = (m0 * e0 + m1 * e1 + m2 * e2 + m3 * e3 +
                 o0 * e4 + o1 * e5 + o2 * e6 + o3 * e7) * inv;
        }
        acc[kk] = v;
        ss += v * v;
    }
    #pragma unroll
    for (int o = 16; o; o >>= 1) ss += __shfl_xor_sync(0xFFFFFFFFu, ss, o);
    if ((tid & 31) == 0) s_red[tid >> 5] = ss;
    __syncthreads();
    float tot = s_red[0] + s_red[1] + s_red[2] + s_red[3];
    float scale = rsqrtf(tot * (1.0f / 512.0f) + 1e-6f);

    #pragma unroll
    for (int kk = 0; kk < 4; ++kk) {
        int d = tid + kk * 128;
        s_out[d] = acc[kk] * scale * norm_w[d];
    }
    __syncthreads();
    if (tid < 32) {  // RoPE on dims 448..511
        float e = s_out[448 + 2 * tid], o = s_out[449 + 2 * tid];
        float cs = cosb[((size_t)b * 1024 + c) * 32 + tid];
        float sn = sinb[((size_t)b * 1024 + c) * 32 + tid];
        s_out[448 + 2 * tid] = e * cs - o * sn;
        s_out[449 + 2 * tid] = e * sn + o * cs;
    }
    __syncthreads();
    float* op = out + ((size_t)b * 1024 + c) * 512;
    #pragma unroll
    for (int kk = 0; kk < 4; ++kk) {
        int d = tid + kk * 128;
        op[d] = s_out[d];
    }
}

// ------------------------------ launcher -------------------------------------
extern "C" void kernel_launch(void* const* d_in, const int* in_sizes, int n_in,
                              void* d_out, int out_size) {
    const float* x    = (const float*)d_in[0];
    const float* cosb = (const float*)d_in[1];
    const float* sinb = (const float*)d_in[2];
    const float* wkv  = (const float*)d_in[3];
    const float* wg   = (const float*)d_in[4];
    const float* ape  = (const float*)d_in[5];
    const float* nw   = (const float*)d_in[6];
    float* out = (float*)d_out;

    cudaFuncSetAttribute(gemm_kernel,
                         cudaFuncAttributeMaxDynamicSharedMemorySize, SMEM_BYTES);

    round_x_kernel<<<32768, 256>>>(reinterpret_cast<const float4*>(x));
    round_w_kernel<<<2048, 256>>>(wkv, wg);
    gemm_kernel<<<1024, 256, SMEM_BYTES>>>();
    combine_kernel<<<dim3(1024, 4), 128>>>(cosb, sinb, ape, nw, out);
}

// round 8
// speedup vs baseline: 1.1236x; 1.1236x over previous
#include <cuda_runtime.h>
#include <cstdint>

// DeepseekV4Compressor on GB300 (sm_103, portable target)
// B=4, S=4096, H=4096, HD=512, RATIO=4, C=1024, ROPE=64
//
//  1) round_x_kernel : RNA-round x -> tf32 bits, 16-wide k-transpose -> g_xr
//  2) round_w_kernel : same + interleave W_kv/W_gate at 64-feature granularity
//  3) gemm_kernel    : mma.sync m16n8k8 tf32, CTA 256x128, 512 thr / 16 warps,
//                      LDS.128 fragment loads, 3-stage cp.async pipeline,
//                      fused epilogue y2 = kv * sigmoid(gate) -> g_y2
//  4) combine_kernel : softmax(ape) combine + RMSNorm + RoPE -> out

// ------------------------- static device scratch -----------------------------
static __device__ float g_xr[67108864];   // 256 MB  [16384, 4096]
static __device__ float g_wc[8388608];    //  32 MB  [2048, 4096]
static __device__ float g_y2[16777216];   //  64 MB  [16384, 1024]

// ------------------------------ helpers --------------------------------------
__device__ __forceinline__ float tf32_rna(float f) {
    uint32_t u; asm("cvt.rna.tf32.f32 %0, %1;" : "=r"(u) : "f"(f));
    return __uint_as_float(u);
}
__device__ __forceinline__ uint32_t smem_u32(const void* p) {
    uint32_t a;
    asm("{ .reg .u64 t; cvta.to.shared.u64 t, %1; cvt.u32.u64 %0, t; }" : "=r"(a) : "l"(p));
    return a;
}
__device__ __forceinline__ void cp_async16(uint32_t dst, const void* src) {
    asm volatile("cp.async.cg.shared.global [%0], [%1], 16;" :: "r"(dst), "l"(src));
}
#define CP_COMMIT() asm volatile("cp.async.commit_group;" ::: "memory")

__device__ __forceinline__ void mma_tf32(float& d0, float& d1, float& d2, float& d3,
                                         uint32_t a0, uint32_t a1, uint32_t a2, uint32_t a3,
                                         uint32_t b0, uint32_t b1) {
    asm volatile("mma.sync.aligned.m16n8k8.row.col.f32.tf32.tf32.f32 "
                 "{%0,%1,%2,%3}, {%4,%5,%6,%7}, {%8,%9}, {%0,%1,%2,%3};"
                 : "+f"(d0), "+f"(d1), "+f"(d2), "+f"(d3)
                 : "r"(a0), "r"(a1), "r"(a2), "r"(a3), "r"(b0), "r"(b1));
}
__device__ __forceinline__ float sigmoidf_(float x) {
    return 1.0f / (1.0f + __expf(-x));
}
__device__ __forceinline__ void lds128(uint32_t& r0, uint32_t& r1,
                                       uint32_t& r2, uint32_t& r3, uint32_t a) {
    asm volatile("ld.shared.v4.b32 {%0,%1,%2,%3}, [%4];"
                 : "=r"(r0), "=r"(r1), "=r"(r2), "=r"(r3) : "r"(a));
}

// 16-wide k-transpose: out position 4c+d <- source k = c + 4d (c,d in 0..3).
// Thread t's LDS.128 at byte t*16 then holds {k=t, t+4, t+8, t+12}: the A/B
// fragments for TWO m16n8k8 steps (k-slices [0,8) and [8,16)). Applied to
// both x and W K-dims, so dot products are unchanged.
__device__ __forceinline__ void perm_round16(const float4* in, float4* out) {
    float4 i0 = in[0], i1 = in[1], i2 = in[2], i3 = in[3];
    out[0] = make_float4(tf32_rna(i0.x), tf32_rna(i1.x), tf32_rna(i2.x), tf32_rna(i3.x));
    out[1] = make_float4(tf32_rna(i0.y), tf32_rna(i1.y), tf32_rna(i2.y), tf32_rna(i3.y));
    out[2] = make_float4(tf32_rna(i0.z), tf32_rna(i1.z), tf32_rna(i2.z), tf32_rna(i3.z));
    out[3] = make_float4(tf32_rna(i0.w), tf32_rna(i1.w), tf32_rna(i2.w), tf32_rna(i3.w));
}

// ----------------------------- rounding passes -------------------------------
__global__ void round_x_kernel(const float4* __restrict__ x) {
    size_t gi = (size_t)blockIdx.x * 256 + threadIdx.x;   // 4,194,304 groups of 16
    float4 o[4];
    perm_round16(x + gi * 4, o);
    float4* dst = reinterpret_cast<float4*>(g_xr) + gi * 4;
    dst[0] = o[0]; dst[1] = o[1]; dst[2] = o[2]; dst[3] = o[3];
}

__global__ void round_w_kernel(const float* __restrict__ wkv, const float* __restrict__ wg) {
    int o2 = blockIdx.x;                      // 0..2047 dest row in g_wc
    int nb = o2 >> 7;                         // 128-row block
    int half = (o2 >> 6) & 1;                 // 0 = kv, 1 = gate
    int idx = o2 & 63;
    const float4* src = reinterpret_cast<const float4*>(
        (half ? wg : wkv) + (size_t)(nb * 64 + idx) * 4096);
    float4* dst = reinterpret_cast<float4*>(g_wc + (size_t)o2 * 4096);
    int gq = threadIdx.x;                     // 256 groups of 16 per row
    float4 o[4];
    perm_round16(src + gq * 4, o);
    dst[gq * 4] = o[0]; dst[gq * 4 + 1] = o[1];
    dst[gq * 4 + 2] = o[2]; dst[gq * 4 + 3] = o[3];
}

// --------------------------------- GEMM --------------------------------------
// CTA 256(M) x 128(N), BK=32. 512 threads = 16 warps (4m x 4n), warp 64x32.
// ROWB=192 (== 64 mod 128): LDS.128 fragment loads are phase-conflict-free,
// consecutive rows alternate bank halves.
#define ROWB    192
#define A_BYTES (256 * ROWB)              // 49152
#define B_BYTES (128 * ROWB)              // 24576
#define STAGE   (A_BYTES + B_BYTES)       // 73728
#define SMEM_BYTES (3 * STAGE)            // 221184
#define NT      128                       // K / 32

__device__ __forceinline__ void load_stage(uint32_t sb, int s, int kt,
                                           int bm, int bn, int tid) {
    uint32_t st = sb + (uint32_t)s * STAGE;
    const float* Ag = g_xr + ((size_t)bm * 256) * 4096 + (size_t)kt * 32;
    const float* Bg = g_wc + ((size_t)bn * 128) * 4096 + (size_t)kt * 32;
    #pragma unroll
    for (int i = 0; i < 6; ++i) {
        int q = tid + i * 512;                 // 0..3071 16B-chunks
        if (q < 2048) {                        // A: 256 rows x 8 chunks
            int r = q >> 3, c = q & 7;
            cp_async16(st + (uint32_t)(r * ROWB + c * 16), Ag + (size_t)r * 4096 + c * 4);
        } else {                               // B: 128 rows x 8 chunks
            int q2 = q - 2048;
            int r = q2 >> 3, c = q2 & 7;
            cp_async16(st + A_BYTES + (uint32_t)(r * ROWB + c * 16),
                       Bg + (size_t)r * 4096 + c * 4);
        }
    }
}

__global__ void __launch_bounds__(512, 1) gemm_kernel() {
    extern __shared__ char smem[];
    const uint32_t sb = smem_u32(smem);
    const int tid = threadIdx.x;
    const int lane = tid & 31, wid = tid >> 5;
    const int wm = wid >> 2, wn = wid & 3;     // 4m x 4n warp grid
    const int g = lane >> 2, t = lane & 3;
    const int bn = blockIdx.x & 15;            // n fastest: A panel L2 reuse
    const int bm = blockIdx.x >> 4;

    float acc[4][4][4];                        // [i: m16][j: n8][frag]
    #pragma unroll
    for (int i = 0; i < 4; ++i)
        #pragma unroll
        for (int j = 0; j < 4; ++j)
            #pragma unroll
            for (int r = 0; r < 4; ++r) acc[i][j][r] = 0.0f;

    load_stage(sb, 0, 0, bm, bn, tid); CP_COMMIT();
    load_stage(sb, 1, 1, bm, bn, tid); CP_COMMIT();

    for (int it = 0; it < NT; ++it) {
        asm volatile("cp.async.wait_group 1;" ::: "memory");
        __syncthreads();

        int ld = it + 2;
        if (ld < NT) load_stage(sb, ld % 3, ld, bm, bn, tid);
        CP_COMMIT();

        const uint32_t st = sb + (uint32_t)(it % 3) * STAGE;
        const uint32_t aB = st + (uint32_t)((wm * 64 + g) * ROWB + t * 16);
        const uint32_t bB = st + A_BYTES + (uint32_t)((wn * 32 + g) * ROWB + t * 16);
        #pragma unroll
        for (int ksp = 0; ksp < 2; ++ksp) {    // each ksp covers two k8 steps
            uint32_t ag[4][4], ah[4][4];       // rows g and g+8, 4 m16 tiles
            #pragma unroll
            for (int i = 0; i < 4; ++i) {
                lds128(ag[i][0], ag[i][1], ag[i][2], ag[i][3],
                       aB + i * 16 * ROWB + ksp * 64);
                lds128(ah[i][0], ah[i][1], ah[i][2], ah[i][3],
                       aB + i * 16 * ROWB + 8 * ROWB + ksp * 64);
            }
            #pragma unroll
            for (int j = 0; j < 4; ++j) {
                uint32_t b0, b1, b2, b3;
                lds128(b0, b1, b2, b3, bB + j * 8 * ROWB + ksp * 64);
                #pragma unroll
                for (int i = 0; i < 4; ++i) {
                    mma_tf32(acc[i][j][0], acc[i][j][1], acc[i][j][2], acc[i][j][3],
                             ag[i][0], ah[i][0], ag[i][1], ah[i][1], b0, b1);
                    mma_tf32(acc[i][j][0], acc[i][j][1], acc[i][j][2], acc[i][j][3],
                             ag[i][2], ah[i][2], ag[i][3], ah[i][3], b2, b3);
                }
            }
        }
    }

    // ---------------- epilogue: y2 = kv * sigmoid(gate) ----------------------
    // local n: wn 0,1 -> kv cols [0,64); wn 2,3 -> gate cols [0,64)
    __syncthreads();
    if (wn >= 2) {                             // gate warps: sigmoid -> smem
        #pragma unroll
        for (int i = 0; i < 4; ++i) {
            int row0 = wm * 64 + i * 16 + g;
            #pragma unroll
            for (int j = 0; j < 4; ++j) {
                int col = (wn - 2) * 32 + j * 8 + 2 * t;
                float2 s0 = make_float2(sigmoidf_(acc[i][j][0]), sigmoidf_(acc[i][j][1]));
                float2 s1 = make_float2(sigmoidf_(acc[i][j][2]), sigmoidf_(acc[i][j][3]));
                *reinterpret_cast<float2*>(smem + row0 * 272 + col * 4) = s0;
                *reinterpret_cast<float2*>(smem + (row0 + 8) * 272 + col * 4) = s1;
            }
        }
    }
    __syncthreads();
    if (wn < 2) {                              // kv warps: fuse and store
        #pragma unroll
        for (int i = 0; i < 4; ++i) {
            int row0 = wm * 64 + i * 16 + g;
            #pragma unroll
            for (int j = 0; j < 4; ++j) {
                int col = wn * 32 + j * 8 + 2 * t;
                float2 s0 = *reinterpret_cast<float2*>(smem + row0 * 272 + col * 4);
                float2 s1 = *reinterpret_cast<float2*>(smem + (row0 + 8) * 272 + col * 4);
                float2 y0 = make_float2(acc[i][j][0] * s0.x, acc[i][j][1] * s0.y);
                float2 y1 = make_float2(acc[i][j][2] * s1.x, acc[i][j][3] * s1.y);
                size_t base = ((size_t)(bm * 256 + row0)) * 1024 + (size_t)bn * 64 + col;
                *reinterpret_cast<float2*>(g_y2 + base) = y0;
                *reinterpret_cast<float2*>(g_y2 + base + 8 * 1024) = y1;
            }
        }
    }
}

// ------------------------------- combine -------------------------------------
__global__ void __launch_bounds__(128) combine_kernel(
    const float* __restrict__ cosb, const float* __restrict__ sinb,
    const float* __restrict__ ape,  const float* __restrict__ norm_w,
    float* __restrict__ out)
{
    __shared__ float s_out[512];
    __shared__ float s_red[4];
    const int c = blockIdx.x, b = blockIdx.y;
    const int tid = threadIdx.x;
    const size_t rowb = (size_t)b * 4096 + (size_t)c * 4;

    float acc[4];
    float ss = 0.0f;
    #pragma unroll
    for (int kk = 0; kk < 4; ++kk) {
        const int d = tid + kk * 128;
        float a0 = ape[d],        a1 = ape[1024 + d];
        float a2 = ape[2048 + d], a3 = ape[3072 + d];
        float m0 = g_y2[(rowb + 0) * 1024 + d];
        float m1 = g_y2[(rowb + 1) * 1024 + d];
        float m2 = g_y2[(rowb + 2) * 1024 + d];
        float m3 = g_y2[(rowb + 3) * 1024 + d];
        float v;
        if (c == 0) {
            float mx = fmaxf(fmaxf(a0, a1), fmaxf(a2, a3));
            float e0 = __expf(a0 - mx), e1 = __expf(a1 - mx);
            float e2 = __expf(a2 - mx), e3 = __expf(a3 - mx);
            float inv = 1.0f / (e0 + e1 + e2 + e3);
            v = (m0 * e0 + m1 * e1 + m2 * e2 + m3 * e3) * inv;
        } else {
            float b0 = ape[512 + d],  b1 = ape[1536 + d];
            float b2 = ape[2560 + d], b3 = ape[3584 + d];
            float o0 = g_y2[(rowb - 4 + 0) * 1024 + 512 + d];
            float o1 = g_y2[(rowb - 4 + 1) * 1024 + 512 + d];
            float o2 = g_y2[(rowb - 4 + 2) * 1024 + 512 + d];
            float o3 = g_y2[(rowb - 4 + 3) * 1024 + 512 + d];
            float mx = fmaxf(fmaxf(fmaxf(a0, a1), fmaxf(a2, a3)),
                             fmaxf(fmaxf(b0, b1), fmaxf(b2, b3)));
            float e0 = __expf(a0 - mx), e1 = __expf(a1 - mx);
            float e2 = __expf(a2 - mx), e3 = __expf(a3 - mx);
            float e4 = __expf(b0 - mx), e5 = __expf(b1 - mx);
            float e6 = __expf(b2 - mx), e7 = __expf(b3 - mx);
            float inv = 1.0f / (e0 + e1 + e2 + e3 + e4 + e5 + e6 + e7);
            v = (m0 * e0 + m1 * e1 + m2 * e2 + m3 * e3 +
                 o0 * e4 + o1 * e5 + o2 * e6 + o3 * e7) * inv;
        }
        acc[kk] = v;
        ss += v * v;
    }
    #pragma unroll
    for (int o = 16; o; o >>= 1) ss += __shfl_xor_sync(0xFFFFFFFFu, ss, o);
    if ((tid & 31) == 0) s_red[tid >> 5] = ss;
    __syncthreads();
    float tot = s_red[0] + s_red[1] + s_red[2] + s_red[3];
    float scale = rsqrtf(tot * (1.0f / 512.0f) + 1e-6f);

    #pragma unroll
    for (int kk = 0; kk < 4; ++kk) {
        int d = tid + kk * 128;
        s_out[d] = acc[kk] * scale * norm_w[d];
    }
    __syncthreads();
    if (tid < 32) {  // RoPE on dims 448..511
        float e = s_out[448 + 2 * tid], o = s_out[449 + 2 * tid];
        float cs = cosb[((size_t)b * 1024 + c) * 32 + tid];
        float sn = sinb[((size_t)b * 1024 + c) * 32 + tid];
        s_out[448 + 2 * tid] = e * cs - o * sn;
        s_out[449 + 2 * tid] = e * sn + o * cs;
    }
    __syncthreads();
    float* op = out + ((size_t)b * 1024 + c) * 512;
    #pragma unroll
    for (int kk = 0; kk < 4; ++kk) {
        int d = tid + kk * 128;
        op[d] = s_out[d];
    }
}

// ------------------------------ launcher -------------------------------------
extern "C" void kernel_launch(void* const* d_in, const int* in_sizes, int n_in,
                              void* d_out, int out_size) {
    const float* x    = (const float*)d_in[0];
    const float* cosb = (const float*)d_in[1];
    const float* sinb = (const float*)d_in[2];
    const float* wkv  = (const float*)d_in[3];
    const float* wg   = (const float*)d_in[4];
    const float* ape  = (const float*)d_in[5];
    const float* nw   = (const float*)d_in[6];
    float* out = (float*)d_out;

    cudaFuncSetAttribute(gemm_kernel,
                         cudaFuncAttributeMaxDynamicSharedMemorySize, SMEM_BYTES);

    round_x_kernel<<<16384, 256>>>(reinterpret_cast<const float4*>(x));
    round_w_kernel<<<2048, 256>>>(wkv, wg);
    gemm_kernel<<<1024, 512, SMEM_BYTES>>>();
    combine_kernel<<<dim3(1024, 4), 128>>>(cosb, sinb, ape, nw, out);
}